// round 1
// baseline (speedup 1.0000x reference)
#include <cuda_runtime.h>
#include <math_constants.h>

// Problem constants (G and K are structurally fixed by the reference)
#define GG      32
#define MAXB    16
#define MAXV    1024
#define MAXO    8192
#define MAXS    8
#define CHUNK   1024
#define TPB_MAIN 160
#define F_LOG2PI 1.8378770664093453f

// ---- scratch (static device globals: no allocation allowed) ----
__device__ float4 g_pts4[MAXB * MAXO];          // {px,py,pz,|p|^2}
__device__ float4 g_nrm4[MAXB * MAXO];          // {nx,ny,nz,|n|^2} (obj_normals[...,0:3])
__device__ int    g_gid[MAXV];
__device__ float  g_chol[MAXB * GG * 10];       // l10,l20,l21, 1/l00,1/l11,1/l22, hld, mean xyz
__device__ int    g_active[GG];
__device__ float  g_top5[MAXB * MAXV * MAXS * 5];
__device__ float  g_akey[MAXB * MAXV * MAXS];
__device__ int    g_aidx[MAXB * MAXV * MAXS];
__device__ float  g_w[MAXB * MAXV];
__device__ float  g_sknn[MAXB * MAXV];
__device__ float  g_mn[MAXB * GG];
__device__ float  g_mx[MAXB * GG];
__device__ double g_dacc;
__device__ double g_pacc;

// Branchless sorted insert of 'a' into ascending t0..t4 (keep 5 smallest).
__device__ __forceinline__ void insert5(float a, float& t0, float& t1, float& t2,
                                        float& t3, float& t4) {
    float n0 = fminf(t0, a); a = fmaxf(t0, a);
    float n1 = fminf(t1, a); a = fmaxf(t1, a);
    float n2 = fminf(t2, a); a = fmaxf(t2, a);
    float n3 = fminf(t3, a); a = fmaxf(t3, a);
    float n4 = fminf(t4, a);
    t0 = n0; t1 = n1; t2 = n2; t3 = n3; t4 = n4;
}

// ---- kernel 1: pack points/normals, gid, Cholesky, active flags, zero accs ----
__global__ void prep_kernel(const float* __restrict__ obj_pts,
                            const float* __restrict__ obj_normals,
                            const float* __restrict__ init_verts,
                            const float* __restrict__ init_anchors,
                            const float* __restrict__ contact_gaussians,
                            const float* __restrict__ anchor_verts,
                            int B, int V, int O, int G, int packBlocks) {
    int bi  = blockIdx.x;
    int tid = threadIdx.x;
    if (bi < packBlocks) {
        int i = bi * 256 + tid;
        if (i < B * O) {
            float x = obj_pts[3*i], y = obj_pts[3*i+1], z = obj_pts[3*i+2];
            g_pts4[i] = make_float4(x, y, z, x*x + y*y + z*z);
            const float* nn = obj_normals + (size_t)6 * i;
            float a = nn[0], b = nn[1], c = nn[2];
            g_nrm4[i] = make_float4(a, b, c, a*a + b*b + c*c);
        }
    } else if (bi == packBlocks) {
        // gid[v] = argmin_g dist(init_verts[v], init_anchors[g])  (strict < -> first idx on ties)
        for (int v = tid; v < V; v += 256) {
            float vx = init_verts[3*v], vy = init_verts[3*v+1], vz = init_verts[3*v+2];
            float best = CUDART_INF_F; int bg = 0;
            for (int g = 0; g < G; g++) {
                float dx = vx - init_anchors[3*g];
                float dy = vy - init_anchors[3*g+1];
                float dz = vz - init_anchors[3*g+2];
                float d2 = dx*dx + dy*dy + dz*dz;
                if (d2 < best) { best = d2; bg = g; }
            }
            g_gid[v] = bg;
        }
    } else {
        if (tid == 0) { g_dacc = 0.0; g_pacc = 0.0; }
        for (int i = tid; i < B * G; i += 256) {
            const float* cg = contact_gaussians + (size_t)12 * i;
            float mx_ = cg[0] + anchor_verts[3*i+0];
            float my_ = cg[1] + anchor_verts[3*i+1];
            float mz_ = cg[2] + anchor_verts[3*i+2];
            // cov row-major at cg[3..11]; lower-tri Cholesky
            float a00 = cg[3], a10 = cg[6], a11 = cg[7];
            float a20 = cg[9], a21 = cg[10], a22 = cg[11];
            float l00 = sqrtf(a00);
            float l10 = a10 / l00;
            float l20 = a20 / l00;
            float l11 = sqrtf(a11 - l10 * l10);
            float l21 = (a21 - l20 * l10) / l11;
            float l22 = sqrtf(a22 - l20 * l20 - l21 * l21);
            float hld = logf(l00) + logf(l11) + logf(l22);
            float* C = g_chol + 10 * i;
            C[0] = l10; C[1] = l20; C[2] = l21;
            C[3] = 1.0f / l00; C[4] = 1.0f / l11; C[5] = 1.0f / l22;
            C[6] = hld; C[7] = mx_; C[8] = my_; C[9] = mz_;
        }
        for (int g = tid; g < G; g += 256) {
            int act = 0;
            for (int b = 0; b < B; b++)
                for (int k = 0; k < 12; k++)
                    if (fabsf(contact_gaussians[(size_t)12 * (b * G + g) + k]) > 1e-9f) act = 1;
            g_active[g] = act;
        }
    }
}

// ---- kernel 2: main distance pass (fused knn-top5 keys + nn argmin) ----
__global__ void __launch_bounds__(TPB_MAIN)
dist_kernel(const float* __restrict__ verts, int B, int V, int O, int S) {
    __shared__ float4 smp[CHUNK];
    __shared__ float4 smn[CHUNK];
    int b    = blockIdx.z;
    int ch   = blockIdx.y;
    int base = ch * CHUNK;
    for (int i = threadIdx.x; i < CHUNK; i += TPB_MAIN) {
        int o = base + i;
        if (o < O) { smp[i] = g_pts4[b * O + o]; smn[i] = g_nrm4[b * O + o]; }
        else {
            smp[i] = make_float4(0.f, 0.f, 0.f, CUDART_INF_F);
            smn[i] = make_float4(0.f, 0.f, 0.f, CUDART_INF_F);
        }
    }
    __syncthreads();

    int v = blockIdx.x * TPB_MAIN + threadIdx.x;
    if (v >= V) return;

    const float* vp = verts + (size_t)3 * (b * V + v);
    float c0 = -2.0f * vp[0], c1 = -2.0f * vp[1], c2 = -2.0f * vp[2];
    float t0, t1, t2, t3, t4;
    t0 = t1 = t2 = t3 = t4 = CUDART_INF_F;
    float bk = CUDART_INF_F;
    int bidx = 0x7FFFFFFF;

#pragma unroll 4
    for (int j = 0; j < CHUNK; j++) {
        float4 p = smp[j];
        float kp = fmaf(p.x, c0, fmaf(p.y, c1, fmaf(p.z, c2, p.w)));
        insert5(kp, t0, t1, t2, t3, t4);
        float4 q = smn[j];
        float kn = fmaf(q.x, c0, fmaf(q.y, c1, fmaf(q.z, c2, q.w)));
        bidx = (kn < bk) ? (base + j) : bidx;   // strict <: keeps first index on ties
        bk   = fminf(bk, kn);
    }
    size_t vi = (size_t)(b * V + v);
    float* dst = g_top5 + (vi * S + ch) * 5;
    dst[0] = t0; dst[1] = t1; dst[2] = t2; dst[3] = t3; dst[4] = t4;
    g_akey[vi * S + ch] = bk;
    g_aidx[vi * S + ch] = bidx;
}

// ---- kernel 3: merge partials; knn sums; Gaussian weight w; pen contribution ----
__global__ void merge_kernel(const float* __restrict__ verts,
                             const float* __restrict__ obj_normals,
                             int B, int V, int O, int S, int G) {
    int idx   = blockIdx.x * 256 + threadIdx.x;
    int total = B * V;
    float pc = 0.0f;
    if (idx < total) {
        int b = idx / V;
        int v = idx - b * V;
        const float* vp = verts + (size_t)3 * idx;
        float vx = vp[0], vy = vp[1], vz = vp[2];
        float v2 = vx*vx + vy*vy + vz*vz;

        // merge S partial top-5 lists
        float t0, t1, t2, t3, t4;
        t0 = t1 = t2 = t3 = t4 = CUDART_INF_F;
        const float* part = g_top5 + (size_t)idx * S * 5;
        for (int i = 0; i < S * 5; i++) insert5(part[i], t0, t1, t2, t3, t4);
        float sk = sqrtf(fmaxf(t0 + v2, 0.f)) + sqrtf(fmaxf(t1 + v2, 0.f))
                 + sqrtf(fmaxf(t2 + v2, 0.f)) + sqrtf(fmaxf(t3 + v2, 0.f))
                 + sqrtf(fmaxf(t4 + v2, 0.f));
        g_sknn[idx] = sk;

        // Gaussian weight for this vertex's group
        int g = g_gid[v];
        const float* C = g_chol + 10 * (b * G + g);
        float dx = vx - C[7], dy = vy - C[8], dz = vz - C[9];
        float y0 = dx * C[3];
        float y1 = (dy - C[0] * y0) * C[4];
        float y2 = (dz - C[1] * y0 - C[2] * y1) * C[5];
        float maha = y0*y0 + y1*y1 + y2*y2;
        float logp = -0.5f * (maha + 3.0f * F_LOG2PI) - C[6];
        g_w[idx] = expf(logp);

        // argmin merge (tie -> smaller index)
        float bk = CUDART_INF_F; int bi_ = 0x7FFFFFFF;
        for (int ch = 0; ch < S; ch++) {
            float k = g_akey[(size_t)idx * S + ch];
            int  ii = g_aidx[(size_t)idx * S + ch];
            if (k < bk || (k == bk && ii < bi_)) { bk = k; bi_ = ii; }
        }
        const float* nn = obj_normals + 6 * ((size_t)b * O + bi_);
        float px = nn[0], py = nn[1], pz = nn[2];
        float nx = nn[3], ny = nn[4], nz = nn[5];
        float rx = px - 0.002f * nx, ry = py - 0.002f * ny, rz = pz - 0.002f * nz;
        float dp = nx * (vx - rx) + ny * (vy - ry) + nz * (vz - rz);
        pc = fmaxf(-dp, 0.0f);
    }
    __shared__ float red[256];
    red[threadIdx.x] = pc;
    __syncthreads();
    for (int s = 128; s > 0; s >>= 1) {
        if (threadIdx.x < s) red[threadIdx.x] += red[threadIdx.x + s];
        __syncthreads();
    }
    if (threadIdx.x == 0) atomicAdd(&g_pacc, (double)red[0]);
}

// ---- kernel 4: per (b,g) min/max of w over group's vertices ----
__global__ void stats_kernel(int B, int V, int G) {
    int idx = blockIdx.x * 256 + threadIdx.x;
    if (idx >= B * G) return;
    int b = idx / G, g = idx - b * G;
    float mn = CUDART_INF_F, mx = -CUDART_INF_F;
    const float* wb = g_w + (size_t)b * V;
    for (int v = 0; v < V; v++) {
        if (g_gid[v] == g) {
            float w = wb[v];
            mn = fminf(mn, w);
            mx = fmaxf(mx, w);
        }
    }
    g_mn[idx] = mn;
    g_mx[idx] = mx;
}

// ---- kernel 5: normalized/thresholded weights * knn sums -> d accumulator ----
__global__ void final_kernel(int B, int V, int G) {
    int idx = blockIdx.x * 256 + threadIdx.x;
    float c = 0.0f;
    if (idx < B * V) {
        int b = idx / V, v = idx - b * V;
        int g = g_gid[v];
        float w  = g_w[idx];
        float mn = g_mn[b * G + g], mx = g_mx[b * G + g];
        float wn = (w - mn) / (mx - mn);       // may be NaN if mx==mn
        if (!(wn > 0.01f)) wn = 0.0f;          // NaN-safe threshold (matches jnp.where)
        if (!g_active[g]) wn = 0.0f;
        c = wn * g_sknn[idx];
    }
    __shared__ float red[256];
    red[threadIdx.x] = c;
    __syncthreads();
    for (int s = 128; s > 0; s >>= 1) {
        if (threadIdx.x < s) red[threadIdx.x] += red[threadIdx.x + s];
        __syncthreads();
    }
    if (threadIdx.x == 0) atomicAdd(&g_dacc, (double)red[0]);
}

// ---- kernel 6: write outputs ----
__global__ void out_kernel(float* out, int B, int V, int K, int out_size) {
    if (out_size >= 1) out[0] = (float)(g_dacc / ((double)B * V * K));
    if (out_size >= 2) out[1] = (float)(g_pacc / ((double)B * V));
}

extern "C" void kernel_launch(void* const* d_in, const int* in_sizes, int n_in,
                              void* d_out, int out_size) {
    const float* verts         = (const float*)d_in[0];
    const float* anchor_verts  = (const float*)d_in[1];
    const float* obj_pts       = (const float*)d_in[2];
    const float* cg            = (const float*)d_in[3];
    const float* obj_normals   = (const float*)d_in[4];
    const float* init_verts    = (const float*)d_in[5];
    const float* init_anchors  = (const float*)d_in[6];

    int V = in_sizes[5] / 3;          // 778
    int G = in_sizes[6] / 3;          // 32
    int B = in_sizes[0] / (3 * V);    // 16
    int O = in_sizes[2] / (3 * B);    // 8192
    int K = 5;                        // fixed by setup_inputs (top-5)

    int S = (O + CHUNK - 1) / CHUNK;  // 8
    int packBlocks = (B * O + 255) / 256;

    prep_kernel<<<packBlocks + 2, 256>>>(obj_pts, obj_normals, init_verts,
                                         init_anchors, cg, anchor_verts,
                                         B, V, O, G, packBlocks);

    dim3 grid((V + TPB_MAIN - 1) / TPB_MAIN, S, B);
    dist_kernel<<<grid, TPB_MAIN>>>(verts, B, V, O, S);

    int total = B * V;
    int rb = (total + 255) / 256;
    merge_kernel<<<rb, 256>>>(verts, obj_normals, B, V, O, S, G);
    stats_kernel<<<(B * G + 255) / 256, 256>>>(B, V, G);
    final_kernel<<<rb, 256>>>(B, V, G);
    out_kernel<<<1, 1>>>((float*)d_out, B, V, K, out_size);
}

// round 3
// speedup vs baseline: 2.1137x; 2.1137x over previous
#include <cuda_runtime.h>
#include <math_constants.h>

// Problem constants (G and K are structurally fixed by the reference)
#define GG      32
#define MAXB    16
#define MAXV    1024
#define MAXO    8192
#define MAXS    16
#define CHUNK   512
#define TPB_MAIN 160
#define F_LOG2PI 1.8378770664093453f

// ---- scratch (static device globals: no allocation allowed) ----
__device__ float4 g_pts4[MAXB * MAXO];          // {px,py,pz,|p|^2}
__device__ float4 g_nrm4[MAXB * MAXO];          // {nx,ny,nz,|n|^2} (obj_normals[...,0:3])
__device__ int    g_gid[MAXV];
__device__ float  g_chol[MAXB * GG * 10];       // l10,l20,l21, 1/l00,1/l11,1/l22, hld, mean xyz
__device__ int    g_active[GG];
__device__ float  g_top5[MAXB * MAXV * MAXS * 5];
__device__ float  g_akey[MAXB * MAXV * MAXS];
__device__ int    g_aidx[MAXB * MAXV * MAXS];
__device__ float  g_w[MAXB * MAXV];
__device__ float  g_sknn[MAXB * MAXV];
__device__ int    g_mnbits[MAXB * GG];          // float-as-int atomics (w >= 0)
__device__ int    g_mxbits[MAXB * GG];
__device__ double g_dacc;
__device__ double g_pacc;

// Branchless sorted insert of 'a' into ascending t0..t4 (keep 5 smallest).
__device__ __forceinline__ void insert5(float a, float& t0, float& t1, float& t2,
                                        float& t3, float& t4) {
    float n0 = fminf(t0, a); a = fmaxf(t0, a);
    float n1 = fminf(t1, a); a = fmaxf(t1, a);
    float n2 = fminf(t2, a); a = fmaxf(t2, a);
    float n3 = fminf(t3, a); a = fmaxf(t3, a);
    float n4 = fminf(t4, a);
    t0 = n0; t1 = n1; t2 = n2; t3 = n3; t4 = n4;
}

// ---- kernel 1: pack points/normals, gid, Cholesky, active flags, init accs ----
__global__ void prep_kernel(const float* __restrict__ obj_pts,
                            const float* __restrict__ obj_normals,
                            const float* __restrict__ init_verts,
                            const float* __restrict__ init_anchors,
                            const float* __restrict__ contact_gaussians,
                            const float* __restrict__ anchor_verts,
                            int B, int V, int O, int G, int packBlocks) {
    int bi  = blockIdx.x;
    int tid = threadIdx.x;
    if (bi < packBlocks) {
        int i = bi * 256 + tid;
        if (i < B * O) {
            float x = obj_pts[3*i], y = obj_pts[3*i+1], z = obj_pts[3*i+2];
            g_pts4[i] = make_float4(x, y, z, x*x + y*y + z*z);
            const float* nn = obj_normals + (size_t)6 * i;
            float a = nn[0], b = nn[1], c = nn[2];
            g_nrm4[i] = make_float4(a, b, c, a*a + b*b + c*c);
        }
    } else if (bi == packBlocks) {
        // gid[v] = argmin_g dist(init_verts[v], init_anchors[g])  (strict < -> first idx on ties)
        for (int v = tid; v < V; v += 256) {
            float vx = init_verts[3*v], vy = init_verts[3*v+1], vz = init_verts[3*v+2];
            float best = CUDART_INF_F; int bg = 0;
            for (int g = 0; g < G; g++) {
                float dx = vx - init_anchors[3*g];
                float dy = vy - init_anchors[3*g+1];
                float dz = vz - init_anchors[3*g+2];
                float d2 = dx*dx + dy*dy + dz*dz;
                if (d2 < best) { best = d2; bg = g; }
            }
            g_gid[v] = bg;
        }
    } else {
        if (tid == 0) { g_dacc = 0.0; g_pacc = 0.0; }
        // init group min/max accumulators (w >= 0: int-ordered == float-ordered)
        for (int i = tid; i < B * G; i += 256) {
            g_mnbits[i] = 0x7F800000;   // +inf
            g_mxbits[i] = 0;            // 0.0f (w >= 0 so this acts as -inf)
        }
        for (int i = tid; i < B * G; i += 256) {
            const float* cg = contact_gaussians + (size_t)12 * i;
            float mx_ = cg[0] + anchor_verts[3*i+0];
            float my_ = cg[1] + anchor_verts[3*i+1];
            float mz_ = cg[2] + anchor_verts[3*i+2];
            // cov row-major at cg[3..11]; lower-tri Cholesky
            float a00 = cg[3], a10 = cg[6], a11 = cg[7];
            float a20 = cg[9], a21 = cg[10], a22 = cg[11];
            float l00 = sqrtf(a00);
            float l10 = a10 / l00;
            float l20 = a20 / l00;
            float l11 = sqrtf(a11 - l10 * l10);
            float l21 = (a21 - l20 * l10) / l11;
            float l22 = sqrtf(a22 - l20 * l20 - l21 * l21);
            float hld = logf(l00) + logf(l11) + logf(l22);
            float* C = g_chol + 10 * i;
            C[0] = l10; C[1] = l20; C[2] = l21;
            C[3] = 1.0f / l00; C[4] = 1.0f / l11; C[5] = 1.0f / l22;
            C[6] = hld; C[7] = mx_; C[8] = my_; C[9] = mz_;
        }
        for (int g = tid; g < G; g += 256) {
            int act = 0;
            for (int b = 0; b < B; b++)
                for (int k = 0; k < 12; k++)
                    if (fabsf(contact_gaussians[(size_t)12 * (b * G + g) + k]) > 1e-9f) act = 1;
            g_active[g] = act;
        }
    }
}

// ---- kernel 2: main distance pass (fused knn-top5 keys + nn argmin) ----
__global__ void __launch_bounds__(TPB_MAIN)
dist_kernel(const float* __restrict__ verts, int B, int V, int O, int S) {
    __shared__ float4 smp[CHUNK];
    __shared__ float4 smn[CHUNK];
    int b    = blockIdx.z;
    int ch   = blockIdx.y;
    int base = ch * CHUNK;
    for (int i = threadIdx.x; i < CHUNK; i += TPB_MAIN) {
        int o = base + i;
        if (o < O) { smp[i] = g_pts4[b * O + o]; smn[i] = g_nrm4[b * O + o]; }
        else {
            smp[i] = make_float4(0.f, 0.f, 0.f, CUDART_INF_F);
            smn[i] = make_float4(0.f, 0.f, 0.f, CUDART_INF_F);
        }
    }
    __syncthreads();

    int v = blockIdx.x * TPB_MAIN + threadIdx.x;
    if (v >= V) return;

    const float* vp = verts + (size_t)3 * (b * V + v);
    float c0 = -2.0f * vp[0], c1 = -2.0f * vp[1], c2 = -2.0f * vp[2];
    float t0, t1, t2, t3, t4;
    t0 = t1 = t2 = t3 = t4 = CUDART_INF_F;
    float bk = CUDART_INF_F;
    int bidx = 0x7FFFFFFF;

#pragma unroll 4
    for (int j = 0; j < CHUNK; j++) {
        float4 p = smp[j];
        float kp = fmaf(p.x, c0, fmaf(p.y, c1, fmaf(p.z, c2, p.w)));
        insert5(kp, t0, t1, t2, t3, t4);
        float4 q = smn[j];
        float kn = fmaf(q.x, c0, fmaf(q.y, c1, fmaf(q.z, c2, q.w)));
        bidx = (kn < bk) ? (base + j) : bidx;   // strict <: keeps first index on ties
        bk   = fminf(bk, kn);
    }
    size_t vi = (size_t)(b * V + v);
    float* dst = g_top5 + (vi * S + ch) * 5;
    dst[0] = t0; dst[1] = t1; dst[2] = t2; dst[3] = t3; dst[4] = t4;
    g_akey[vi * S + ch] = bk;
    g_aidx[vi * S + ch] = bidx;
}

// ---- kernel 3: merge partials; knn sums; Gaussian weight w (+ group min/max
//      via int atomics); pen contribution ----
__global__ void merge_kernel(const float* __restrict__ verts,
                             const float* __restrict__ obj_normals,
                             int B, int V, int O, int S, int G) {
    int idx   = blockIdx.x * 256 + threadIdx.x;
    int total = B * V;
    float pc = 0.0f;
    if (idx < total) {
        int b = idx / V;
        int v = idx - b * V;
        const float* vp = verts + (size_t)3 * idx;
        float vx = vp[0], vy = vp[1], vz = vp[2];
        float v2 = vx*vx + vy*vy + vz*vz;

        // merge S partial top-5 lists
        float t0, t1, t2, t3, t4;
        t0 = t1 = t2 = t3 = t4 = CUDART_INF_F;
        const float* part = g_top5 + (size_t)idx * S * 5;
        for (int i = 0; i < S * 5; i++) insert5(part[i], t0, t1, t2, t3, t4);
        float sk = sqrtf(fmaxf(t0 + v2, 0.f)) + sqrtf(fmaxf(t1 + v2, 0.f))
                 + sqrtf(fmaxf(t2 + v2, 0.f)) + sqrtf(fmaxf(t3 + v2, 0.f))
                 + sqrtf(fmaxf(t4 + v2, 0.f));
        g_sknn[idx] = sk;

        // Gaussian weight for this vertex's group
        int g = g_gid[v];
        const float* C = g_chol + 10 * (b * G + g);
        float dx = vx - C[7], dy = vy - C[8], dz = vz - C[9];
        float y0 = dx * C[3];
        float y1 = (dy - C[0] * y0) * C[4];
        float y2 = (dz - C[1] * y0 - C[2] * y1) * C[5];
        float maha = y0*y0 + y1*y1 + y2*y2;
        float logp = -0.5f * (maha + 3.0f * F_LOG2PI) - C[6];
        float w = expf(logp);
        g_w[idx] = w;
        // fused group min/max (w >= 0 -> int order == float order)
        atomicMin(&g_mnbits[b * G + g], __float_as_int(w));
        atomicMax(&g_mxbits[b * G + g], __float_as_int(w));

        // argmin merge (tie -> smaller index)
        float bk = CUDART_INF_F; int bi_ = 0x7FFFFFFF;
        for (int ch = 0; ch < S; ch++) {
            float k = g_akey[(size_t)idx * S + ch];
            int  ii = g_aidx[(size_t)idx * S + ch];
            if (k < bk || (k == bk && ii < bi_)) { bk = k; bi_ = ii; }
        }
        const float* nn = obj_normals + 6 * ((size_t)b * O + bi_);
        float px = nn[0], py = nn[1], pz = nn[2];
        float nx = nn[3], ny = nn[4], nz = nn[5];
        float rx = px - 0.002f * nx, ry = py - 0.002f * ny, rz = pz - 0.002f * nz;
        float dp = nx * (vx - rx) + ny * (vy - ry) + nz * (vz - rz);
        pc = fmaxf(-dp, 0.0f);
    }
    __shared__ float red[256];
    red[threadIdx.x] = pc;
    __syncthreads();
    for (int s = 128; s > 0; s >>= 1) {
        if (threadIdx.x < s) red[threadIdx.x] += red[threadIdx.x + s];
        __syncthreads();
    }
    if (threadIdx.x == 0) atomicAdd(&g_pacc, (double)red[0]);
}

// ---- kernel 4: normalized/thresholded weights * knn sums -> d accumulator ----
__global__ void final_kernel(int B, int V, int G) {
    int idx = blockIdx.x * 256 + threadIdx.x;
    float c = 0.0f;
    if (idx < B * V) {
        int b = idx / V, v = idx - b * V;
        int g = g_gid[v];
        float w  = g_w[idx];
        float mn = __int_as_float(g_mnbits[b * G + g]);
        float mx = __int_as_float(g_mxbits[b * G + g]);
        float wn = (w - mn) / (mx - mn);       // may be NaN if mx==mn
        if (!(wn > 0.01f)) wn = 0.0f;          // NaN-safe threshold (matches jnp.where)
        if (!g_active[g]) wn = 0.0f;
        c = wn * g_sknn[idx];
    }
    __shared__ float red[256];
    red[threadIdx.x] = c;
    __syncthreads();
    for (int s = 128; s > 0; s >>= 1) {
        if (threadIdx.x < s) red[threadIdx.x] += red[threadIdx.x + s];
        __syncthreads();
    }
    if (threadIdx.x == 0) atomicAdd(&g_dacc, (double)red[0]);
}

// ---- kernel 5: write outputs ----
__global__ void out_kernel(float* out, int B, int V, int K, int out_size) {
    if (out_size >= 1) out[0] = (float)(g_dacc / ((double)B * V * K));
    if (out_size >= 2) out[1] = (float)(g_pacc / ((double)B * V));
}

extern "C" void kernel_launch(void* const* d_in, const int* in_sizes, int n_in,
                              void* d_out, int out_size) {
    const float* verts         = (const float*)d_in[0];
    const float* anchor_verts  = (const float*)d_in[1];
    const float* obj_pts       = (const float*)d_in[2];
    const float* cg            = (const float*)d_in[3];
    const float* obj_normals   = (const float*)d_in[4];
    const float* init_verts    = (const float*)d_in[5];
    const float* init_anchors  = (const float*)d_in[6];

    int V = in_sizes[5] / 3;          // 778
    int G = in_sizes[6] / 3;          // 32
    int B = in_sizes[0] / (3 * V);    // 16
    int O = in_sizes[2] / (3 * B);    // 8192
    int K = 5;                        // fixed by setup_inputs (top-5)

    int S = (O + CHUNK - 1) / CHUNK;  // 16
    int packBlocks = (B * O + 255) / 256;

    prep_kernel<<<packBlocks + 2, 256>>>(obj_pts, obj_normals, init_verts,
                                         init_anchors, cg, anchor_verts,
                                         B, V, O, G, packBlocks);

    dim3 grid((V + TPB_MAIN - 1) / TPB_MAIN, S, B);
    dist_kernel<<<grid, TPB_MAIN>>>(verts, B, V, O, S);

    int total = B * V;
    int rb = (total + 255) / 256;
    merge_kernel<<<rb, 256>>>(verts, obj_normals, B, V, O, S, G);
    final_kernel<<<rb, 256>>>(B, V, G);
    out_kernel<<<1, 1>>>((float*)d_out, B, V, K, out_size);
}